// round 9
// baseline (speedup 1.0000x reference)
#include <cuda_runtime.h>
#include <cuda_fp16.h>
#include <cstdint>
#include <cstddef>

#define B_DIM 8192
#define HIN   4096
#define HOUT  4096
#define KE    4160          // 4096 + 32 LoRA + 32 zero pad = 65 chunks of K=64

// ---------------- device scratch: single fp16 plane per operand ----------------
__device__ __align__(16) __half g_xp[(size_t)B_DIM * KE];
__device__ __align__(16) __half g_wp[(size_t)HOUT * KE];

// ---------------- helpers ----------------
__device__ __forceinline__ uint32_t smem_u32(const void* p) {
    uint32_t a;
    asm("{ .reg .u64 t; cvta.to.shared.u64 t, %1; cvt.u32.u64 %0, t; }" : "=r"(a) : "l"(p));
    return a;
}

__device__ __forceinline__ uint2 pack4h(float4 f) {
    __half2 a = __floats2half2_rn(f.x, f.y);
    __half2 b = __floats2half2_rn(f.z, f.w);
    uint2 r;
    r.x = *reinterpret_cast<uint32_t*>(&a);
    r.y = *reinterpret_cast<uint32_t*>(&b);
    return r;
}

__device__ __forceinline__ void cpa16(uint32_t dst, const void* src) {
    asm volatile("cp.async.cg.shared.global [%0], [%1], 16;" :: "r"(dst), "l"(src));
}

__device__ __forceinline__ void ldm4(uint32_t* r, uint32_t addr) {
    asm volatile("ldmatrix.sync.aligned.m8n8.x4.shared.b16 {%0,%1,%2,%3}, [%4];"
                 : "=r"(r[0]), "=r"(r[1]), "=r"(r[2]), "=r"(r[3]) : "r"(addr));
}

__device__ __forceinline__ void mma16816(float* c, const uint32_t* a, uint32_t b0, uint32_t b1) {
    asm volatile(
        "mma.sync.aligned.m16n8k16.row.col.f32.f16.f16.f32 "
        "{%0,%1,%2,%3}, {%4,%5,%6,%7}, {%8,%9}, {%0,%1,%2,%3};"
        : "+f"(c[0]), "+f"(c[1]), "+f"(c[2]), "+f"(c[3])
        : "r"(a[0]), "r"(a[1]), "r"(a[2]), "r"(a[3]), "r"(b0), "r"(b1));
}

// ====== Combined prep kernel ======
// Blocks [0,256):   LoRA-A over 32-row x tiles + fused x->fp16 conversion + aw/pad cols
// Blocks [256,768): W->fp16 conversion (8 rows each) + scaling*qb cols + pad
#define NLORA_BLK 256
#define NW_BLK    512

__global__ void __launch_bounds__(256) prep_kernel(
    const float* __restrict__ x, const float* __restrict__ tkw, const float* __restrict__ qa,
    const float* __restrict__ W, const float* __restrict__ qb, const float* __restrict__ scaling)
{
    const int tid  = threadIdx.x;
    const int lane = tid & 31, w = tid >> 5;

    if (blockIdx.x < NLORA_BLK) {
        // ---------------- LoRA-A + x conversion, 32 batch rows ----------------
        __shared__ float xs[32][64];
        __shared__ float qs[64][33];
        const int b0 = blockIdx.x * 32;

        float acc[4] = {0.f, 0.f, 0.f, 0.f};

        for (int k0 = 0; k0 < HIN; k0 += 64) {
            __syncthreads();
            #pragma unroll
            for (int i = 0; i < 2; i++) {            // x tile: 512 float4
                int v = tid + i * 256;
                int r = v >> 4, c = (v & 15) << 2;
                *reinterpret_cast<float4*>(&xs[r][c]) =
                    *reinterpret_cast<const float4*>(x + (size_t)(b0 + r) * HIN + k0 + c);
            }
            #pragma unroll
            for (int i = 0; i < 2; i++) {            // qa tile: 512 float4, transposed
                int v = tid + i * 256;
                int kr = v >> 4, c = (v & 15) << 2;
                float4 f = *reinterpret_cast<const float4*>(qa + (size_t)kr * HIN + k0 + c);
                qs[c + 0][kr] = f.x; qs[c + 1][kr] = f.y;
                qs[c + 2][kr] = f.z; qs[c + 3][kr] = f.w;
            }
            __syncthreads();
            // fused x -> fp16 plane (from staged smem tile)
            #pragma unroll
            for (int i = 0; i < 2; i++) {
                int v = tid + i * 256;
                int r = v >> 4, c = (v & 15) << 2;
                float4 f = *reinterpret_cast<const float4*>(&xs[r][c]);
                *reinterpret_cast<uint2*>(g_xp + (size_t)(b0 + r) * KE + k0 + c) = pack4h(f);
            }
            #pragma unroll
            for (int kk = 0; kk < 64; kk += 4) {
                float q0 = qs[kk][lane], q1 = qs[kk + 1][lane];
                float q2 = qs[kk + 2][lane], q3 = qs[kk + 3][lane];
                #pragma unroll
                for (int i = 0; i < 4; i++) {
                    float4 xv = *reinterpret_cast<const float4*>(&xs[w * 4 + i][kk]);
                    acc[i] += xv.x * q0 + xv.y * q1 + xv.z * q2 + xv.w * q3;
                }
            }
        }
        #pragma unroll
        for (int i = 0; i < 4; i++) {
            int b = b0 + w * 4 + i;
            float v = acc[i] * tkw[b * 4 + (lane >> 3)];
            g_xp[(size_t)b * KE + 4096 + lane] = __float2half(v);
        }
        // zero pad cols [4128, 4160): 32 rows x 4 uint2
        if (tid < 128) {
            int r = tid >> 2, seg = tid & 3;
            *reinterpret_cast<uint2*>(g_xp + (size_t)(b0 + r) * KE + 4128 + seg * 8) =
                make_uint2(0u, 0u);
        }
    } else {
        // ---------------- W conversion, 8 rows, warp-per-row ----------------
        const int o0 = (blockIdx.x - NLORA_BLK) * 8;
        const int o  = o0 + w;
        const size_t rb = (size_t)o * KE;
        const float* wr = W + (size_t)o * HIN;
        #pragma unroll 8
        for (int i = 0; i < 32; i++) {
            int c4 = (i * 32 + lane) << 2;
            float4 f = *reinterpret_cast<const float4*>(wr + c4);
            *reinterpret_cast<uint2*>(g_wp + rb + c4) = pack4h(f);
        }
        // LoRA cols [4096,4128): 8 threads per row
        if (tid < 64) {
            int row = o0 + (tid >> 3), t8 = tid & 7;
            int c4 = 4096 + t8 * 4;
            int kk = t8 >> 1, rr = (t8 & 1) * 4;     // kr = kk*8 + rr..rr+3
            const float* p = qb + ((size_t)kk * HOUT + row) * 8 + rr;
            float sc = scaling[row];
            float4 f = make_float4(p[0] * sc, p[1] * sc, p[2] * sc, p[3] * sc);
            *reinterpret_cast<uint2*>(g_wp + (size_t)row * KE + c4) = pack4h(f);
        } else if (tid < 96) {
            // zero pad [4128,4160): 4 uint2 per row x 8 rows
            int row = o0 + ((tid - 64) >> 2), seg = tid & 3;
            *reinterpret_cast<uint2*>(g_wp + (size_t)row * KE + 4128 + seg * 8) =
                make_uint2(0u, 0u);
        }
    }
}

// ================= GEMM (single-pass fp16, B-pipelined) =================
// 512 threads (16 warps, 4x4), CTA tile M=128 x N=256, K=64 chunks.
// Smem row = 128B = 64 fp16; 3-stage cp.async ring, wait_group 1.
#define A_OFF   0
#define W_OFF   16384
#define STAGE_B 49152
#define NSTAGE  3
#define SMEM_TOTAL (NSTAGE * STAGE_B)
#define NCHUNK  65

__device__ __forceinline__ void issue_stage(uint32_t st, int ch, int m0, int n0, int tid)
{
    const int r8 = tid >> 3, sg = tid & 7;           // row group, 16B segment
    const size_t kofs = (size_t)ch * 64 + sg * 8;
    const uint32_t sgb = (uint32_t)sg * 16u;
    #pragma unroll
    for (int j = 0; j < 2; j++) {                    // A: 128 rows
        int row = r8 + 64 * j;
        uint32_t d = (uint32_t)row * 128u + (sgb ^ ((uint32_t)(row & 7) << 4));
        cpa16(st + A_OFF + d, g_xp + (size_t)(m0 + row) * KE + kofs);
    }
    #pragma unroll
    for (int j = 0; j < 4; j++) {                    // W: 256 rows
        int row = r8 + 64 * j;
        uint32_t d = (uint32_t)row * 128u + (sgb ^ ((uint32_t)(row & 7) << 4));
        cpa16(st + W_OFF + d, g_wp + (size_t)(n0 + row) * KE + kofs);
    }
    asm volatile("cp.async.commit_group;" ::: "memory");
}

__global__ void __launch_bounds__(512, 1) fused_gemm_kernel(float* __restrict__ out)
{
    extern __shared__ char smem[];
    const int tid = threadIdx.x;
    const int wid = tid >> 5, lid = tid & 31;
    const int wr = wid >> 2, wc = wid & 3;           // 4x4 warp grid
    const int n0 = blockIdx.x * 256;
    const int m0 = blockIdx.y * 128;
    const uint32_t sbase = smem_u32(smem);
    const int lr = lid & 15;
    const uint32_t lhb = (uint32_t)(lid >> 4) * 16u;

    uint32_t abase[2], arx[2], bbase[4], brx[4];
    #pragma unroll
    for (int t = 0; t < 2; t++) {
        uint32_t row = (uint32_t)(wr * 32 + t * 16 + lr);
        abase[t] = row * 128u; arx[t] = (row & 7u) << 4;
    }
    #pragma unroll
    for (int g = 0; g < 4; g++) {
        uint32_t row = (uint32_t)(wc * 64 + g * 16 + lr);
        bbase[g] = row * 128u; brx[g] = (row & 7u) << 4;
    }

    float acc[2][8][4];
    #pragma unroll
    for (int t = 0; t < 2; t++)
        #pragma unroll
        for (int j = 0; j < 8; j++)
            #pragma unroll
            for (int e = 0; e < 4; e++) acc[t][j][e] = 0.f;

    issue_stage(sbase + 0 * STAGE_B, 0, m0, n0, tid);
    issue_stage(sbase + 1 * STAGE_B, 1, m0, n0, tid);

    int sidx = 0;
    for (int ch = 0; ch < NCHUNK; ch++) {
        const uint32_t st = sbase + sidx * STAGE_B;
        const uint32_t sa = st + A_OFF, sw = st + W_OFF;

        asm volatile("cp.async.wait_group 1;" ::: "memory");
        __syncthreads();
        if (ch + 2 < NCHUNK) {
            int ps = sidx + 2; if (ps >= NSTAGE) ps -= NSTAGE;
            issue_stage(sbase + ps * STAGE_B, ch + 2, m0, n0, tid);
        } else {
            asm volatile("cp.async.commit_group;" ::: "memory");  // keep group count in step
        }

        #pragma unroll
        for (int ks = 0; ks < 4; ks++) {             // 4 k16 steps per K=64 chunk
            const uint32_t chb = (uint32_t)ks * 32u + lhb;
            uint32_t ah[2][4];
            ldm4(ah[0], sa + abase[0] + (chb ^ arx[0]));
            ldm4(ah[1], sa + abase[1] + (chb ^ arx[1]));

            uint32_t bfrag[2][4];                    // double-buffered B fragments
            ldm4(bfrag[0], sw + bbase[0] + (chb ^ brx[0]));
            #pragma unroll
            for (int g = 0; g < 4; g++) {
                const int cur = g & 1;
                if (g < 3)
                    ldm4(bfrag[cur ^ 1], sw + bbase[g + 1] + (chb ^ brx[g + 1]));
                #pragma unroll
                for (int t = 0; t < 2; t++) {
                    #pragma unroll
                    for (int j2 = 0; j2 < 2; j2++)
                        mma16816(acc[t][g * 2 + j2], ah[t],
                                 bfrag[cur][j2], bfrag[cur][j2 + 2]);
                }
            }
        }
        if (++sidx >= NSTAGE) sidx = 0;
    }

    // Epilogue: direct fp32 STG (float2 sector-coalesced)
    #pragma unroll
    for (int t = 0; t < 2; t++) {
        int mr = m0 + wr * 32 + t * 16 + (lid >> 2);
        #pragma unroll
        for (int j = 0; j < 8; j++) {
            int col = n0 + wc * 64 + j * 8 + (lid & 3) * 2;
            *reinterpret_cast<float2*>(out + (size_t)mr * HOUT + col) =
                make_float2(acc[t][j][0], acc[t][j][1]);
            *reinterpret_cast<float2*>(out + (size_t)(mr + 8) * HOUT + col) =
                make_float2(acc[t][j][2], acc[t][j][3]);
        }
    }
}

// ================= launch =================
extern "C" void kernel_launch(void* const* d_in, const int* in_sizes, int n_in,
                              void* d_out, int out_size) {
    const float* x       = (const float*)d_in[0];
    const float* tkw     = (const float*)d_in[1];
    const float* W       = (const float*)d_in[2];
    const float* qa      = (const float*)d_in[3];
    const float* qb      = (const float*)d_in[4];
    const float* scaling = (const float*)d_in[5];
    float* out = (float*)d_out;

    prep_kernel<<<NLORA_BLK + NW_BLK, 256>>>(x, tkw, qa, W, qb, scaling);

    cudaFuncSetAttribute(fused_gemm_kernel,
                         cudaFuncAttributeMaxDynamicSharedMemorySize, SMEM_TOTAL);
    dim3 grid(HOUT / 256, B_DIM / 128);
    fused_gemm_kernel<<<grid, 512, SMEM_TOTAL>>>(out);
}

// round 10
// speedup vs baseline: 1.2131x; 1.2131x over previous
#include <cuda_runtime.h>
#include <cuda_fp16.h>
#include <cstdint>
#include <cstddef>

#define B_DIM 8192
#define HIN   4096
#define HOUT  4096
#define KE    4160          // 4096 + 32 LoRA + 32 zero pad = 65 chunks of K=64

// ---------------- device scratch ----------------
__device__ __align__(16) __half g_xp[(size_t)B_DIM * KE];
__device__ __align__(16) __half g_wp[(size_t)HOUT * KE];
__device__ __align__(16) __half g_qa16[32 * HIN];

// ---------------- helpers ----------------
__device__ __forceinline__ uint32_t smem_u32(const void* p) {
    uint32_t a;
    asm("{ .reg .u64 t; cvta.to.shared.u64 t, %1; cvt.u32.u64 %0, t; }" : "=r"(a) : "l"(p));
    return a;
}

__device__ __forceinline__ uint2 pack4h(float4 f) {
    __half2 a = __floats2half2_rn(f.x, f.y);
    __half2 b = __floats2half2_rn(f.z, f.w);
    uint2 r;
    r.x = *reinterpret_cast<uint32_t*>(&a);
    r.y = *reinterpret_cast<uint32_t*>(&b);
    return r;
}

__device__ __forceinline__ void cpa16(uint32_t dst, const void* src) {
    asm volatile("cp.async.cg.shared.global [%0], [%1], 16;" :: "r"(dst), "l"(src));
}

__device__ __forceinline__ void ldm4(uint32_t* r, uint32_t addr) {
    asm volatile("ldmatrix.sync.aligned.m8n8.x4.shared.b16 {%0,%1,%2,%3}, [%4];"
                 : "=r"(r[0]), "=r"(r[1]), "=r"(r[2]), "=r"(r[3]) : "r"(addr));
}

__device__ __forceinline__ void ldm2(uint32_t* r, uint32_t addr) {
    asm volatile("ldmatrix.sync.aligned.m8n8.x2.shared.b16 {%0,%1}, [%2];"
                 : "=r"(r[0]), "=r"(r[1]) : "r"(addr));
}

__device__ __forceinline__ void mma16816(float* c, const uint32_t* a, uint32_t b0, uint32_t b1) {
    asm volatile(
        "mma.sync.aligned.m16n8k16.row.col.f32.f16.f16.f32 "
        "{%0,%1,%2,%3}, {%4,%5,%6,%7}, {%8,%9}, {%0,%1,%2,%3};"
        : "+f"(c[0]), "+f"(c[1]), "+f"(c[2]), "+f"(c[3])
        : "r"(a[0]), "r"(a[1]), "r"(a[2]), "r"(a[3]), "r"(b0), "r"(b1));
}

// ================= cvt_qa: qa fp32 -> fp16 =================
__global__ void __launch_bounds__(256) cvt_qa_kernel(const float* __restrict__ qa)
{
    const int kr = blockIdx.x, tid = threadIdx.x;
    #pragma unroll
    for (int i = 0; i < 4; i++) {
        int c4 = (tid + i * 256) << 2;
        float4 f = *reinterpret_cast<const float4*>(qa + (size_t)kr * HIN + c4);
        *reinterpret_cast<uint2*>(g_qa16 + (size_t)kr * HIN + c4) = pack4h(f);
    }
}

// ================= cvt_x: x fp32 -> fp16 plane, 4 rows/block, + pad =================
__global__ void __launch_bounds__(256) cvt_x_kernel(const float* __restrict__ x)
{
    const int b0 = blockIdx.x * 4, tid = threadIdx.x;
    const int r = tid >> 6, t64 = tid & 63;
    const size_t rb = (size_t)(b0 + r) * KE;
    const float* xr = x + (size_t)(b0 + r) * HIN;
    #pragma unroll
    for (int i = 0; i < 16; i++) {
        int c4 = (t64 + i * 64) << 2;
        float4 f = *reinterpret_cast<const float4*>(xr + c4);
        *reinterpret_cast<uint2*>(g_xp + rb + c4) = pack4h(f);
    }
    if (tid < 16) {  // zero pad cols [4128,4160): 4 rows x 4 uint2
        int rr = tid >> 2, seg = tid & 3;
        *reinterpret_cast<uint2*>(g_xp + (size_t)(b0 + rr) * KE + 4128 + seg * 8) =
            make_uint2(0u, 0u);
    }
}

// ====== cvt_w: W fp32 -> fp16 plane (8 rows, warp-per-row) + scaling*qb cols + pad ======
__global__ void __launch_bounds__(256) cvt_w_kernel(
    const float* __restrict__ W, const float* __restrict__ qb, const float* __restrict__ scaling)
{
    const int tid = threadIdx.x;
    const int lane = tid & 31, w = tid >> 5;
    const int o0 = blockIdx.x * 8;
    const int o  = o0 + w;
    const size_t rb = (size_t)o * KE;
    const float* wr = W + (size_t)o * HIN;
    #pragma unroll 8
    for (int i = 0; i < 32; i++) {
        int c4 = (i * 32 + lane) << 2;
        float4 f = *reinterpret_cast<const float4*>(wr + c4);
        *reinterpret_cast<uint2*>(g_wp + rb + c4) = pack4h(f);
    }
    if (tid < 64) {  // LoRA cols [4096,4128)
        int row = o0 + (tid >> 3), t8 = tid & 7;
        int c4 = 4096 + t8 * 4;
        int kk = t8 >> 1, rr = (t8 & 1) * 4;         // kr = kk*8 + rr..rr+3
        const float* p = qb + ((size_t)kk * HOUT + row) * 8 + rr;
        float sc = scaling[row];
        float4 f = make_float4(p[0] * sc, p[1] * sc, p[2] * sc, p[3] * sc);
        *reinterpret_cast<uint2*>(g_wp + (size_t)row * KE + c4) = pack4h(f);
    } else if (tid < 96) {  // zero pad [4128,4160)
        int row = o0 + ((tid - 64) >> 2), seg = tid & 3;
        *reinterpret_cast<uint2*>(g_wp + (size_t)row * KE + 4128 + seg * 8) =
            make_uint2(0u, 0u);
    }
}

// ================= lora_aw: aw = (x_fp16 @ qa16^T) * tkw -> x-plane cols [4096,4128) ======
// Block: 256 threads (8 warps), M=32 rows, N=32 full, K=4096 in 64-chunks.
// Warp w: mt = w&1 (16 m-rows), nt = w>>1 (8 n-cols). 3-stage cp.async ring.
#define LA_OFF  0
#define LB_OFF  4096
#define LSTAGE  8192
#define LNSTAGE 3

__device__ __forceinline__ void lora_issue(uint32_t st, int ch, int b0, int tid)
{
    const int row = tid >> 3, sg = tid & 7;          // 32 rows x 8 segs
    const uint32_t d = (uint32_t)row * 128u + ((uint32_t)(sg * 16) ^ ((uint32_t)(row & 7) << 4));
    const size_t kofs = (size_t)ch * 64 + sg * 8;
    cpa16(st + LA_OFF + d, g_xp + (size_t)(b0 + row) * KE + kofs);
    cpa16(st + LB_OFF + d, g_qa16 + (size_t)row * HIN + kofs);
    asm volatile("cp.async.commit_group;" ::: "memory");
}

__global__ void __launch_bounds__(256) lora_aw_kernel(const float* __restrict__ tkw)
{
    __shared__ __align__(128) char smem[LNSTAGE * LSTAGE];
    const int tid = threadIdx.x;
    const int wid = tid >> 5, lid = tid & 31;
    const int mt = wid & 1, nt = wid >> 1;
    const int b0 = blockIdx.x * 32;
    const uint32_t sbase = smem_u32(smem);
    const int lr = lid & 15;
    const uint32_t lhb = (uint32_t)(lid >> 4) * 16u;

    const uint32_t arow = (uint32_t)(mt * 16 + lr);
    const uint32_t abase = arow * 128u, arx = (arow & 7u) << 4;
    const uint32_t brow = (uint32_t)(nt * 8 + (lid & 7));
    const uint32_t bbase = brow * 128u, brx = (brow & 7u) << 4;
    const uint32_t bhalf = ((uint32_t)(lid >> 3) & 1u) * 16u;

    float c[4] = {0.f, 0.f, 0.f, 0.f};

    lora_issue(sbase + 0 * LSTAGE, 0, b0, tid);
    lora_issue(sbase + 1 * LSTAGE, 1, b0, tid);

    int sidx = 0;
    for (int ch = 0; ch < 64; ch++) {
        const uint32_t st = sbase + sidx * LSTAGE;
        asm volatile("cp.async.wait_group 1;" ::: "memory");
        __syncthreads();
        if (ch + 2 < 64) {
            int ps = sidx + 2; if (ps >= LNSTAGE) ps -= LNSTAGE;
            lora_issue(sbase + ps * LSTAGE, ch + 2, b0, tid);
        } else {
            asm volatile("cp.async.commit_group;" ::: "memory");
        }
        #pragma unroll
        for (int ks = 0; ks < 4; ks++) {
            const uint32_t kb = (uint32_t)ks * 32u;
            uint32_t a[4], b[2];
            ldm4(a, st + LA_OFF + abase + ((kb + lhb) ^ arx));
            ldm2(b, st + LB_OFF + bbase + ((kb + bhalf) ^ brx));
            mma16816(c, a, b[0], b[1]);
        }
        if (++sidx >= LNSTAGE) sidx = 0;
    }

    // epilogue: scale by tkw (expert k = nt) and store fp16 into x-plane
    int m0r = b0 + mt * 16 + (lid >> 2);
    int col = nt * 8 + (lid & 3) * 2;
    float t0 = tkw[m0r * 4 + nt];
    float t1 = tkw[(m0r + 8) * 4 + nt];
    __half* p0 = g_xp + (size_t)m0r * KE + 4096 + col;
    __half* p1 = g_xp + (size_t)(m0r + 8) * KE + 4096 + col;
    p0[0] = __float2half(c[0] * t0);
    p0[1] = __float2half(c[1] * t0);
    p1[0] = __float2half(c[2] * t1);
    p1[1] = __float2half(c[3] * t1);
}

// ================= GEMM (single-pass fp16, B-pipelined) =================
// 512 threads (16 warps, 4x4), CTA tile M=128 x N=256, K=64 chunks.
// Smem row = 128B = 64 fp16; 3-stage cp.async ring, wait_group 1.
#define A_OFF   0
#define W_OFF   16384
#define STAGE_B 49152
#define NSTAGE  3
#define SMEM_TOTAL (NSTAGE * STAGE_B)
#define NCHUNK  65

__device__ __forceinline__ void issue_stage(uint32_t st, int ch, int m0, int n0, int tid)
{
    const int r8 = tid >> 3, sg = tid & 7;           // row group, 16B segment
    const size_t kofs = (size_t)ch * 64 + sg * 8;
    const uint32_t sgb = (uint32_t)sg * 16u;
    #pragma unroll
    for (int j = 0; j < 2; j++) {                    // A: 128 rows
        int row = r8 + 64 * j;
        uint32_t d = (uint32_t)row * 128u + (sgb ^ ((uint32_t)(row & 7) << 4));
        cpa16(st + A_OFF + d, g_xp + (size_t)(m0 + row) * KE + kofs);
    }
    #pragma unroll
    for (int j = 0; j < 4; j++) {                    // W: 256 rows
        int row = r8 + 64 * j;
        uint32_t d = (uint32_t)row * 128u + (sgb ^ ((uint32_t)(row & 7) << 4));
        cpa16(st + W_OFF + d, g_wp + (size_t)(n0 + row) * KE + kofs);
    }
    asm volatile("cp.async.commit_group;" ::: "memory");
}

__global__ void __launch_bounds__(512, 1) fused_gemm_kernel(float* __restrict__ out)
{
    extern __shared__ char smem[];
    const int tid = threadIdx.x;
    const int wid = tid >> 5, lid = tid & 31;
    const int wr = wid >> 2, wc = wid & 3;           // 4x4 warp grid
    const int n0 = blockIdx.x * 256;
    const int m0 = blockIdx.y * 128;
    const uint32_t sbase = smem_u32(smem);
    const int lr = lid & 15;
    const uint32_t lhb = (uint32_t)(lid >> 4) * 16u;

    uint32_t abase[2], arx[2], bbase[4], brx[4];
    #pragma unroll
    for (int t = 0; t < 2; t++) {
        uint32_t row = (uint32_t)(wr * 32 + t * 16 + lr);
        abase[t] = row * 128u; arx[t] = (row & 7u) << 4;
    }
    #pragma unroll
    for (int g = 0; g < 4; g++) {
        uint32_t row = (uint32_t)(wc * 64 + g * 16 + lr);
        bbase[g] = row * 128u; brx[g] = (row & 7u) << 4;
    }

    float acc[2][8][4];
    #pragma unroll
    for (int t = 0; t < 2; t++)
        #pragma unroll
        for (int j = 0; j < 8; j++)
            #pragma unroll
            for (int e = 0; e < 4; e++) acc[t][j][e] = 0.f;

    issue_stage(sbase + 0 * STAGE_B, 0, m0, n0, tid);
    issue_stage(sbase + 1 * STAGE_B, 1, m0, n0, tid);

    int sidx = 0;
    for (int ch = 0; ch < NCHUNK; ch++) {
        const uint32_t st = sbase + sidx * STAGE_B;
        const uint32_t sa = st + A_OFF, sw = st + W_OFF;

        asm volatile("cp.async.wait_group 1;" ::: "memory");
        __syncthreads();
        if (ch + 2 < NCHUNK) {
            int ps = sidx + 2; if (ps >= NSTAGE) ps -= NSTAGE;
            issue_stage(sbase + ps * STAGE_B, ch + 2, m0, n0, tid);
        } else {
            asm volatile("cp.async.commit_group;" ::: "memory");  // keep group count in step
        }

        #pragma unroll
        for (int ks = 0; ks < 4; ks++) {             // 4 k16 steps per K=64 chunk
            const uint32_t chb = (uint32_t)ks * 32u + lhb;
            uint32_t ah[2][4];
            ldm4(ah[0], sa + abase[0] + (chb ^ arx[0]));
            ldm4(ah[1], sa + abase[1] + (chb ^ arx[1]));

            uint32_t bfrag[2][4];                    // double-buffered B fragments
            ldm4(bfrag[0], sw + bbase[0] + (chb ^ brx[0]));
            #pragma unroll
            for (int g = 0; g < 4; g++) {
                const int cur = g & 1;
                if (g < 3)
                    ldm4(bfrag[cur ^ 1], sw + bbase[g + 1] + (chb ^ brx[g + 1]));
                #pragma unroll
                for (int t = 0; t < 2; t++) {
                    #pragma unroll
                    for (int j2 = 0; j2 < 2; j2++)
                        mma16816(acc[t][g * 2 + j2], ah[t],
                                 bfrag[cur][j2], bfrag[cur][j2 + 2]);
                }
            }
        }
        if (++sidx >= NSTAGE) sidx = 0;
    }

    // Epilogue: direct fp32 STG (float2 sector-coalesced)
    #pragma unroll
    for (int t = 0; t < 2; t++) {
        int mr = m0 + wr * 32 + t * 16 + (lid >> 2);
        #pragma unroll
        for (int j = 0; j < 8; j++) {
            int col = n0 + wc * 64 + j * 8 + (lid & 3) * 2;
            *reinterpret_cast<float2*>(out + (size_t)mr * HOUT + col) =
                make_float2(acc[t][j][0], acc[t][j][1]);
            *reinterpret_cast<float2*>(out + (size_t)(mr + 8) * HOUT + col) =
                make_float2(acc[t][j][2], acc[t][j][3]);
        }
    }
}

// ================= launch =================
extern "C" void kernel_launch(void* const* d_in, const int* in_sizes, int n_in,
                              void* d_out, int out_size) {
    const float* x       = (const float*)d_in[0];
    const float* tkw     = (const float*)d_in[1];
    const float* W       = (const float*)d_in[2];
    const float* qa      = (const float*)d_in[3];
    const float* qb      = (const float*)d_in[4];
    const float* scaling = (const float*)d_in[5];
    float* out = (float*)d_out;

    cvt_qa_kernel<<<32, 256>>>(qa);
    cvt_w_kernel<<<HOUT / 8, 256>>>(W, qb, scaling);
    cvt_x_kernel<<<B_DIM / 4, 256>>>(x);
    lora_aw_kernel<<<B_DIM / 32, 256>>>(tkw);

    cudaFuncSetAttribute(fused_gemm_kernel,
                         cudaFuncAttributeMaxDynamicSharedMemorySize, SMEM_TOTAL);
    dim3 grid(HOUT / 256, B_DIM / 128);
    fused_gemm_kernel<<<grid, 512, SMEM_TOTAL>>>(out);
}

// round 11
// speedup vs baseline: 1.3045x; 1.0753x over previous
#include <cuda_runtime.h>
#include <cuda_fp16.h>
#include <cstdint>
#include <cstddef>

#define B_DIM 8192
#define HIN   4096
#define HOUT  4096
#define KE    4160          // 4096 + 32 LoRA + 32 zero pad = 65 chunks of K=64

// ---------------- device scratch ----------------
__device__ __align__(16) __half g_xp[(size_t)B_DIM * KE];
__device__ __align__(16) __half g_wp[(size_t)HOUT * KE];
__device__ __align__(16) __half g_qa16[32 * HIN];

// ---------------- helpers ----------------
__device__ __forceinline__ uint32_t smem_u32(const void* p) {
    uint32_t a;
    asm("{ .reg .u64 t; cvta.to.shared.u64 t, %1; cvt.u32.u64 %0, t; }" : "=r"(a) : "l"(p));
    return a;
}

__device__ __forceinline__ uint2 pack4h(float4 f) {
    __half2 a = __floats2half2_rn(f.x, f.y);
    __half2 b = __floats2half2_rn(f.z, f.w);
    uint2 r;
    r.x = *reinterpret_cast<uint32_t*>(&a);
    r.y = *reinterpret_cast<uint32_t*>(&b);
    return r;
}

__device__ __forceinline__ void cpa16(uint32_t dst, const void* src) {
    asm volatile("cp.async.cg.shared.global [%0], [%1], 16;" :: "r"(dst), "l"(src));
}

__device__ __forceinline__ void ldm4(uint32_t* r, uint32_t addr) {
    asm volatile("ldmatrix.sync.aligned.m8n8.x4.shared.b16 {%0,%1,%2,%3}, [%4];"
                 : "=r"(r[0]), "=r"(r[1]), "=r"(r[2]), "=r"(r[3]) : "r"(addr));
}

__device__ __forceinline__ void ldm2(uint32_t* r, uint32_t addr) {
    asm volatile("ldmatrix.sync.aligned.m8n8.x2.shared.b16 {%0,%1}, [%2];"
                 : "=r"(r[0]), "=r"(r[1]) : "r"(addr));
}

__device__ __forceinline__ void mma16816(float* c, const uint32_t* a, uint32_t b0, uint32_t b1) {
    asm volatile(
        "mma.sync.aligned.m16n8k16.row.col.f32.f16.f16.f32 "
        "{%0,%1,%2,%3}, {%4,%5,%6,%7}, {%8,%9}, {%0,%1,%2,%3};"
        : "+f"(c[0]), "+f"(c[1]), "+f"(c[2]), "+f"(c[3])
        : "r"(a[0]), "r"(a[1]), "r"(a[2]), "r"(a[3]), "r"(b0), "r"(b1));
}

// ================= cvt_qa: qa fp32 -> fp16 =================
__global__ void __launch_bounds__(256) cvt_qa_kernel(const float* __restrict__ qa)
{
    const int kr = blockIdx.x, tid = threadIdx.x;
    #pragma unroll
    for (int i = 0; i < 4; i++) {
        int c4 = (tid + i * 256) << 2;
        float4 f = *reinterpret_cast<const float4*>(qa + (size_t)kr * HIN + c4);
        *reinterpret_cast<uint2*>(g_qa16 + (size_t)kr * HIN + c4) = pack4h(f);
    }
}

// ================= cvt_x: x fp32 -> fp16 plane, 4 rows/block, + pad =================
__global__ void __launch_bounds__(256) cvt_x_kernel(const float* __restrict__ x)
{
    const int b0 = blockIdx.x * 4, tid = threadIdx.x;
    const int r = tid >> 6, t64 = tid & 63;
    const size_t rb = (size_t)(b0 + r) * KE;
    const float* xr = x + (size_t)(b0 + r) * HIN;
    #pragma unroll
    for (int i = 0; i < 16; i++) {
        int c4 = (t64 + i * 64) << 2;
        float4 f = *reinterpret_cast<const float4*>(xr + c4);
        *reinterpret_cast<uint2*>(g_xp + rb + c4) = pack4h(f);
    }
    if (tid < 16) {  // zero pad cols [4128,4160): 4 rows x 4 uint2
        int rr = tid >> 2, seg = tid & 3;
        *reinterpret_cast<uint2*>(g_xp + (size_t)(b0 + rr) * KE + 4128 + seg * 8) =
            make_uint2(0u, 0u);
    }
}

// ====== cvt_w: W fp32 -> fp16 plane (8 rows, warp-per-row) + scaling*qb cols + pad ======
__global__ void __launch_bounds__(256) cvt_w_kernel(
    const float* __restrict__ W, const float* __restrict__ qb, const float* __restrict__ scaling)
{
    const int tid = threadIdx.x;
    const int lane = tid & 31, w = tid >> 5;
    const int o0 = blockIdx.x * 8;
    const int o  = o0 + w;
    const size_t rb = (size_t)o * KE;
    const float* wr = W + (size_t)o * HIN;
    #pragma unroll 8
    for (int i = 0; i < 32; i++) {
        int c4 = (i * 32 + lane) << 2;
        float4 f = *reinterpret_cast<const float4*>(wr + c4);
        *reinterpret_cast<uint2*>(g_wp + rb + c4) = pack4h(f);
    }
    if (tid < 64) {  // LoRA cols [4096,4128)
        int row = o0 + (tid >> 3), t8 = tid & 7;
        int c4 = 4096 + t8 * 4;
        int kk = t8 >> 1, rr = (t8 & 1) * 4;         // kr = kk*8 + rr..rr+3
        const float* p = qb + ((size_t)kk * HOUT + row) * 8 + rr;
        float sc = scaling[row];
        float4 f = make_float4(p[0] * sc, p[1] * sc, p[2] * sc, p[3] * sc);
        *reinterpret_cast<uint2*>(g_wp + (size_t)row * KE + c4) = pack4h(f);
    } else if (tid < 96) {  // zero pad [4128,4160)
        int row = o0 + ((tid - 64) >> 2), seg = tid & 3;
        *reinterpret_cast<uint2*>(g_wp + (size_t)row * KE + 4128 + seg * 8) =
            make_uint2(0u, 0u);
    }
}

// ================= lora_aw: aw = (x_fp16 @ qa16^T) * tkw -> x-plane cols [4096,4128) ======
#define LA_OFF  0
#define LB_OFF  4096
#define LSTAGE  8192
#define LNSTAGE 3

__device__ __forceinline__ void lora_issue(uint32_t st, int ch, int b0, int tid)
{
    const int row = tid >> 3, sg = tid & 7;          // 32 rows x 8 segs
    const uint32_t d = (uint32_t)row * 128u + ((uint32_t)(sg * 16) ^ ((uint32_t)(row & 7) << 4));
    const size_t kofs = (size_t)ch * 64 + sg * 8;
    cpa16(st + LA_OFF + d, g_xp + (size_t)(b0 + row) * KE + kofs);
    cpa16(st + LB_OFF + d, g_qa16 + (size_t)row * HIN + kofs);
    asm volatile("cp.async.commit_group;" ::: "memory");
}

__global__ void __launch_bounds__(256) lora_aw_kernel(const float* __restrict__ tkw)
{
    __shared__ __align__(128) char smem[LNSTAGE * LSTAGE];
    const int tid = threadIdx.x;
    const int wid = tid >> 5, lid = tid & 31;
    const int mt = wid & 1, nt = wid >> 1;
    const int b0 = blockIdx.x * 32;
    const uint32_t sbase = smem_u32(smem);
    const int lr = lid & 15;
    const uint32_t lhb = (uint32_t)(lid >> 4) * 16u;

    const uint32_t arow = (uint32_t)(mt * 16 + lr);
    const uint32_t abase = arow * 128u, arx = (arow & 7u) << 4;
    const uint32_t brow = (uint32_t)(nt * 8 + (lid & 7));
    const uint32_t bbase = brow * 128u, brx = (brow & 7u) << 4;
    const uint32_t bhalf = ((uint32_t)(lid >> 3) & 1u) * 16u;

    float c[4] = {0.f, 0.f, 0.f, 0.f};

    lora_issue(sbase + 0 * LSTAGE, 0, b0, tid);
    lora_issue(sbase + 1 * LSTAGE, 1, b0, tid);

    int sidx = 0;
    for (int ch = 0; ch < 64; ch++) {
        const uint32_t st = sbase + sidx * LSTAGE;
        asm volatile("cp.async.wait_group 1;" ::: "memory");
        __syncthreads();
        if (ch + 2 < 64) {
            int ps = sidx + 2; if (ps >= LNSTAGE) ps -= LNSTAGE;
            lora_issue(sbase + ps * LSTAGE, ch + 2, b0, tid);
        } else {
            asm volatile("cp.async.commit_group;" ::: "memory");
        }
        #pragma unroll
        for (int ks = 0; ks < 4; ks++) {
            const uint32_t kb = (uint32_t)ks * 32u;
            uint32_t a[4], b[2];
            ldm4(a, st + LA_OFF + abase + ((kb + lhb) ^ arx));
            ldm2(b, st + LB_OFF + bbase + ((kb + bhalf) ^ brx));
            mma16816(c, a, b[0], b[1]);
        }
        if (++sidx >= LNSTAGE) sidx = 0;
    }

    int m0r = b0 + mt * 16 + (lid >> 2);
    int col = nt * 8 + (lid & 3) * 2;
    float t0 = tkw[m0r * 4 + nt];
    float t1 = tkw[(m0r + 8) * 4 + nt];
    __half* p0 = g_xp + (size_t)m0r * KE + 4096 + col;
    __half* p1 = g_xp + (size_t)(m0r + 8) * KE + 4096 + col;
    p0[0] = __float2half(c[0] * t0);
    p0[1] = __float2half(c[1] * t0);
    p1[0] = __float2half(c[2] * t1);
    p1[1] = __float2half(c[3] * t1);
}

// ================= GEMM: 2 CTAs/SM, 256 threads, tile 128x128, K=64 chunks =============
// 8 warps in 4x2 grid (warp tile 32x64); smem row = 128B; 3-stage ring, wait_group 1.
#define A_OFF   0
#define W_OFF   16384
#define STAGE_B 32768
#define NSTAGE  3
#define SMEM_TOTAL (NSTAGE * STAGE_B)
#define NCHUNK  65

__device__ __forceinline__ void issue_stage(uint32_t st, int ch, int m0, int n0, int tid)
{
    const int r8 = tid >> 3, sg = tid & 7;           // 32 base rows, 8 segments
    const size_t kofs = (size_t)ch * 64 + sg * 8;
    const uint32_t sgb = (uint32_t)sg * 16u;
    #pragma unroll
    for (int j = 0; j < 4; j++) {                    // A: 128 rows
        int row = r8 + 32 * j;
        uint32_t d = (uint32_t)row * 128u + (sgb ^ ((uint32_t)(row & 7) << 4));
        cpa16(st + A_OFF + d, g_xp + (size_t)(m0 + row) * KE + kofs);
    }
    #pragma unroll
    for (int j = 0; j < 4; j++) {                    // W: 128 rows
        int row = r8 + 32 * j;
        uint32_t d = (uint32_t)row * 128u + (sgb ^ ((uint32_t)(row & 7) << 4));
        cpa16(st + W_OFF + d, g_wp + (size_t)(n0 + row) * KE + kofs);
    }
    asm volatile("cp.async.commit_group;" ::: "memory");
}

__global__ void __launch_bounds__(256, 2) fused_gemm_kernel(float* __restrict__ out)
{
    extern __shared__ char smem[];
    const int tid = threadIdx.x;
    const int wid = tid >> 5, lid = tid & 31;
    const int wr = wid >> 1, wc = wid & 1;           // 4x2 warp grid
    const int n0 = blockIdx.x * 128;
    const int m0 = blockIdx.y * 128;
    const uint32_t sbase = smem_u32(smem);
    const int lr = lid & 15;
    const uint32_t lhb = (uint32_t)(lid >> 4) * 16u;

    uint32_t abase[2], arx[2], bbase[4], brx[4];
    #pragma unroll
    for (int t = 0; t < 2; t++) {
        uint32_t row = (uint32_t)(wr * 32 + t * 16 + lr);
        abase[t] = row * 128u; arx[t] = (row & 7u) << 4;
    }
    #pragma unroll
    for (int g = 0; g < 4; g++) {
        uint32_t row = (uint32_t)(wc * 64 + g * 16 + lr);
        bbase[g] = row * 128u; brx[g] = (row & 7u) << 4;
    }

    float acc[2][8][4];
    #pragma unroll
    for (int t = 0; t < 2; t++)
        #pragma unroll
        for (int j = 0; j < 8; j++)
            #pragma unroll
            for (int e = 0; e < 4; e++) acc[t][j][e] = 0.f;

    issue_stage(sbase + 0 * STAGE_B, 0, m0, n0, tid);
    issue_stage(sbase + 1 * STAGE_B, 1, m0, n0, tid);

    int sidx = 0;
    for (int ch = 0; ch < NCHUNK; ch++) {
        const uint32_t st = sbase + sidx * STAGE_B;
        const uint32_t sa = st + A_OFF, sw = st + W_OFF;

        asm volatile("cp.async.wait_group 1;" ::: "memory");
        __syncthreads();
        if (ch + 2 < NCHUNK) {
            int ps = sidx + 2; if (ps >= NSTAGE) ps -= NSTAGE;
            issue_stage(sbase + ps * STAGE_B, ch + 2, m0, n0, tid);
        } else {
            asm volatile("cp.async.commit_group;" ::: "memory");  // keep group count in step
        }

        #pragma unroll
        for (int ks = 0; ks < 4; ks++) {             // 4 k16 steps per K=64 chunk
            const uint32_t chb = (uint32_t)ks * 32u + lhb;
            uint32_t ah[2][4];
            ldm4(ah[0], sa + abase[0] + (chb ^ arx[0]));
            ldm4(ah[1], sa + abase[1] + (chb ^ arx[1]));

            uint32_t bfrag[2][4];                    // double-buffered B fragments
            ldm4(bfrag[0], sw + bbase[0] + (chb ^ brx[0]));
            #pragma unroll
            for (int g = 0; g < 4; g++) {
                const int cur = g & 1;
                if (g < 3)
                    ldm4(bfrag[cur ^ 1], sw + bbase[g + 1] + (chb ^ brx[g + 1]));
                #pragma unroll
                for (int t = 0; t < 2; t++) {
                    #pragma unroll
                    for (int j2 = 0; j2 < 2; j2++)
                        mma16816(acc[t][g * 2 + j2], ah[t],
                                 bfrag[cur][j2], bfrag[cur][j2 + 2]);
                }
            }
        }
        if (++sidx >= NSTAGE) sidx = 0;
    }

    // Epilogue: direct fp32 STG (float2 sector-coalesced)
    #pragma unroll
    for (int t = 0; t < 2; t++) {
        int mr = m0 + wr * 32 + t * 16 + (lid >> 2);
        #pragma unroll
        for (int j = 0; j < 8; j++) {
            int col = n0 + wc * 64 + j * 8 + (lid & 3) * 2;
            *reinterpret_cast<float2*>(out + (size_t)mr * HOUT + col) =
                make_float2(acc[t][j][0], acc[t][j][1]);
            *reinterpret_cast<float2*>(out + (size_t)(mr + 8) * HOUT + col) =
                make_float2(acc[t][j][2], acc[t][j][3]);
        }
    }
}

// ================= launch =================
extern "C" void kernel_launch(void* const* d_in, const int* in_sizes, int n_in,
                              void* d_out, int out_size) {
    const float* x       = (const float*)d_in[0];
    const float* tkw     = (const float*)d_in[1];
    const float* W       = (const float*)d_in[2];
    const float* qa      = (const float*)d_in[3];
    const float* qb      = (const float*)d_in[4];
    const float* scaling = (const float*)d_in[5];
    float* out = (float*)d_out;

    cvt_qa_kernel<<<32, 256>>>(qa);
    cvt_w_kernel<<<HOUT / 8, 256>>>(W, qb, scaling);
    cvt_x_kernel<<<B_DIM / 4, 256>>>(x);
    lora_aw_kernel<<<B_DIM / 32, 256>>>(tkw);

    cudaFuncSetAttribute(fused_gemm_kernel,
                         cudaFuncAttributeMaxDynamicSharedMemorySize, SMEM_TOTAL);
    dim3 grid(HOUT / 128, B_DIM / 128);
    fused_gemm_kernel<<<grid, 256, SMEM_TOTAL>>>(out);
}

// round 12
// speedup vs baseline: 1.3047x; 1.0001x over previous
#include <cuda_runtime.h>
#include <cuda_fp16.h>
#include <cstdint>
#include <cstddef>

#define B_DIM 8192
#define HIN   4096
#define HOUT  4096
#define KE    4160          // 4096 + 32 LoRA + 32 zero pad = 65 chunks of K=64

// ---------------- device scratch ----------------
__device__ __align__(16) __half g_xp[(size_t)B_DIM * KE];
__device__ __align__(16) __half g_wp[(size_t)HOUT * KE];
__device__ __align__(16) __half g_qa16[32 * HIN];

// ---------------- helpers ----------------
__device__ __forceinline__ uint32_t smem_u32(const void* p) {
    uint32_t a;
    asm("{ .reg .u64 t; cvta.to.shared.u64 t, %1; cvt.u32.u64 %0, t; }" : "=r"(a) : "l"(p));
    return a;
}

__device__ __forceinline__ uint2 pack4h(float4 f) {
    __half2 a = __floats2half2_rn(f.x, f.y);
    __half2 b = __floats2half2_rn(f.z, f.w);
    uint2 r;
    r.x = *reinterpret_cast<uint32_t*>(&a);
    r.y = *reinterpret_cast<uint32_t*>(&b);
    return r;
}

__device__ __forceinline__ void cpa16(uint32_t dst, const void* src) {
    asm volatile("cp.async.cg.shared.global [%0], [%1], 16;" :: "r"(dst), "l"(src));
}

__device__ __forceinline__ void ldm4(uint32_t* r, uint32_t addr) {
    asm volatile("ldmatrix.sync.aligned.m8n8.x4.shared.b16 {%0,%1,%2,%3}, [%4];"
                 : "=r"(r[0]), "=r"(r[1]), "=r"(r[2]), "=r"(r[3]) : "r"(addr));
}

__device__ __forceinline__ void ldm2(uint32_t* r, uint32_t addr) {
    asm volatile("ldmatrix.sync.aligned.m8n8.x2.shared.b16 {%0,%1}, [%2];"
                 : "=r"(r[0]), "=r"(r[1]) : "r"(addr));
}

__device__ __forceinline__ void mma16816(float* c, const uint32_t* a, uint32_t b0, uint32_t b1) {
    asm volatile(
        "mma.sync.aligned.m16n8k16.row.col.f32.f16.f16.f32 "
        "{%0,%1,%2,%3}, {%4,%5,%6,%7}, {%8,%9}, {%0,%1,%2,%3};"
        : "+f"(c[0]), "+f"(c[1]), "+f"(c[2]), "+f"(c[3])
        : "r"(a[0]), "r"(a[1]), "r"(a[2]), "r"(a[3]), "r"(b0), "r"(b1));
}

// ================= cvt_qa: qa fp32 -> fp16 (tiny) =================
__global__ void __launch_bounds__(256) cvt_qa_kernel(const float* __restrict__ qa)
{
    const int kr = blockIdx.x, tid = threadIdx.x;
    #pragma unroll
    for (int i = 0; i < 4; i++) {
        int c4 = (tid + i * 256) << 2;
        float4 f = *reinterpret_cast<const float4*>(qa + (size_t)kr * HIN + c4);
        *reinterpret_cast<uint2*>(g_qa16 + (size_t)kr * HIN + c4) = pack4h(f);
    }
}

// ================= Fused prep kernel =================
// Blocks [0,256):   LoRA+x-convert: 32 x-rows each. Per K=64 chunk: LDG fp32 x ->
//                   convert in regs -> store fp16 to g_xp AND swizzled smem tile ->
//                   ldmatrix+mma against pre-converted qa. aw*tkw -> x-plane LoRA cols.
// Blocks [256,768): W->fp16 conversion (8 rows, warp-per-row) + scaling*qb cols + pad.
#define NLORA_BLK 256
// smem layout for LoRA blocks: XA0@0 XA1@4096 QB0@8192 QB1@12288 QB2@16384 (20KB)
#define PXA(s) ((uint32_t)(s) * 4096u)
#define PQB(q) (8192u + (uint32_t)(q) * 4096u)

__global__ void __launch_bounds__(256) prep_kernel(
    const float* __restrict__ x, const float* __restrict__ tkw,
    const float* __restrict__ W, const float* __restrict__ qb,
    const float* __restrict__ scaling)
{
    const int tid  = threadIdx.x;
    const int lane = tid & 31, w = tid >> 5;

    if (blockIdx.x < NLORA_BLK) {
        __shared__ __align__(128) char smem[5 * 4096];
        const uint32_t sbase = smem_u32(smem);
        const int b0 = blockIdx.x * 32;
        const int lid = lane, wid = w;
        const int mt = wid & 1, nt = wid >> 1;
        const int lr = lid & 15;
        const uint32_t lhb = (uint32_t)(lid >> 4) * 16u;

        // loader mapping (x): 2 float4 per thread per chunk
        const int xr0 = tid >> 4, xc = (tid & 15) << 2;    // rows tid>>4 and +16
        const uint32_t xd0 = (uint32_t)xr0 * 128u + (((uint32_t)xc * 2u) ^ ((uint32_t)(xr0 & 7) << 4));
        const int xr1 = xr0 + 16;
        const uint32_t xd1 = (uint32_t)xr1 * 128u + (((uint32_t)xc * 2u) ^ ((uint32_t)(xr1 & 7) << 4));
        // loader mapping (qa): 1 cpa16 per thread per chunk
        const int qr = tid >> 3, qs = tid & 7;
        const uint32_t qd = (uint32_t)qr * 128u + (((uint32_t)qs * 16u) ^ ((uint32_t)(qr & 7) << 4));

        // mma addressing (identical to validated lora_aw)
        const uint32_t arow = (uint32_t)(mt * 16 + lr);
        const uint32_t abase = arow * 128u, arx = (arow & 7u) << 4;
        const uint32_t brow = (uint32_t)(nt * 8 + (lid & 7));
        const uint32_t bbase = brow * 128u, brx = (brow & 7u) << 4;
        const uint32_t bhalf = ((uint32_t)(lid >> 3) & 1u) * 16u;

        float c[4] = {0.f, 0.f, 0.f, 0.f};
        float4 f0, f1;

        // prologue: chunk0 x in regs -> convert; qa chunks 0,1 in flight
        f0 = *reinterpret_cast<const float4*>(x + (size_t)(b0 + xr0) * HIN + xc);
        f1 = *reinterpret_cast<const float4*>(x + (size_t)(b0 + xr1) * HIN + xc);
        cpa16(sbase + PQB(0) + qd, g_qa16 + (size_t)qr * HIN + qs * 8);
        asm volatile("cp.async.commit_group;" ::: "memory");
        {
            uint2 h0 = pack4h(f0), h1 = pack4h(f1);
            *reinterpret_cast<uint2*>(smem + PXA(0) + xd0) = h0;
            *reinterpret_cast<uint2*>(smem + PXA(0) + xd1) = h1;
            *reinterpret_cast<uint2*>(g_xp + (size_t)(b0 + xr0) * KE + xc) = h0;
            *reinterpret_cast<uint2*>(g_xp + (size_t)(b0 + xr1) * KE + xc) = h1;
        }
        f0 = *reinterpret_cast<const float4*>(x + (size_t)(b0 + xr0) * HIN + 64 + xc);
        f1 = *reinterpret_cast<const float4*>(x + (size_t)(b0 + xr1) * HIN + 64 + xc);
        cpa16(sbase + PQB(1) + qd, g_qa16 + (size_t)qr * HIN + 64 + qs * 8);
        asm volatile("cp.async.commit_group;" ::: "memory");

        for (int ch = 0; ch < 64; ch++) {
            const int s = ch & 1;
            const int q = ch % 3;
            asm volatile("cp.async.wait_group 1;" ::: "memory");
            __syncthreads();
            if (ch + 1 < 64) {                       // convert x[ch+1] -> XA[1-s] + g_xp
                const int k1 = (ch + 1) * 64;
                uint2 h0 = pack4h(f0), h1 = pack4h(f1);
                *reinterpret_cast<uint2*>(smem + PXA(1 - s) + xd0) = h0;
                *reinterpret_cast<uint2*>(smem + PXA(1 - s) + xd1) = h1;
                *reinterpret_cast<uint2*>(g_xp + (size_t)(b0 + xr0) * KE + k1 + xc) = h0;
                *reinterpret_cast<uint2*>(g_xp + (size_t)(b0 + xr1) * KE + k1 + xc) = h1;
            }
            if (ch + 2 < 64) {                       // prefetch x[ch+2] regs + qa[ch+2] cpa
                const int k2 = (ch + 2) * 64;
                f0 = *reinterpret_cast<const float4*>(x + (size_t)(b0 + xr0) * HIN + k2 + xc);
                f1 = *reinterpret_cast<const float4*>(x + (size_t)(b0 + xr1) * HIN + k2 + xc);
                cpa16(sbase + PQB((ch + 2) % 3) + qd, g_qa16 + (size_t)qr * HIN + k2 + qs * 8);
            }
            asm volatile("cp.async.commit_group;" ::: "memory");

            #pragma unroll
            for (int ks = 0; ks < 4; ks++) {
                const uint32_t kb = (uint32_t)ks * 32u;
                uint32_t a[4], b[2];
                ldm4(a, sbase + PXA(s) + abase + ((kb + lhb) ^ arx));
                ldm2(b, sbase + PQB(q) + bbase + ((kb + bhalf) ^ brx));
                mma16816(c, a, b[0], b[1]);
            }
        }

        // epilogue: aw * tkw -> x-plane cols [4096,4128), fp16
        int m0r = b0 + mt * 16 + (lid >> 2);
        int col = nt * 8 + (lid & 3) * 2;
        float t0 = tkw[m0r * 4 + nt];
        float t1 = tkw[(m0r + 8) * 4 + nt];
        __half* p0 = g_xp + (size_t)m0r * KE + 4096 + col;
        __half* p1 = g_xp + (size_t)(m0r + 8) * KE + 4096 + col;
        p0[0] = __float2half(c[0] * t0);
        p0[1] = __float2half(c[1] * t0);
        p1[0] = __float2half(c[2] * t1);
        p1[1] = __float2half(c[3] * t1);
        // zero pad cols [4128,4160): 32 rows x 4 uint2
        if (tid < 128) {
            int r = tid >> 2, seg = tid & 3;
            *reinterpret_cast<uint2*>(g_xp + (size_t)(b0 + r) * KE + 4128 + seg * 8) =
                make_uint2(0u, 0u);
        }
    } else {
        // ---------------- W conversion, 8 rows, warp-per-row ----------------
        const int o0 = (blockIdx.x - NLORA_BLK) * 8;
        const int o  = o0 + w;
        const size_t rb = (size_t)o * KE;
        const float* wr = W + (size_t)o * HIN;
        #pragma unroll 8
        for (int i = 0; i < 32; i++) {
            int c4 = (i * 32 + lane) << 2;
            float4 f = *reinterpret_cast<const float4*>(wr + c4);
            *reinterpret_cast<uint2*>(g_wp + rb + c4) = pack4h(f);
        }
        if (tid < 64) {  // LoRA cols [4096,4128)
            int row = o0 + (tid >> 3), t8 = tid & 7;
            int c4 = 4096 + t8 * 4;
            int kk = t8 >> 1, rr = (t8 & 1) * 4;     // kr = kk*8 + rr..rr+3
            const float* p = qb + ((size_t)kk * HOUT + row) * 8 + rr;
            float sc = scaling[row];
            float4 f = make_float4(p[0] * sc, p[1] * sc, p[2] * sc, p[3] * sc);
            *reinterpret_cast<uint2*>(g_wp + (size_t)row * KE + c4) = pack4h(f);
        } else if (tid < 96) {  // zero pad [4128,4160)
            int row = o0 + ((tid - 64) >> 2), seg = tid & 3;
            *reinterpret_cast<uint2*>(g_wp + (size_t)row * KE + 4128 + seg * 8) =
                make_uint2(0u, 0u);
        }
    }
}

// ================= GEMM: 2 CTAs/SM, 256 threads, tile 128x128, K=64 chunks =============
// (unchanged from round 11 — best measured configuration)
#define A_OFF   0
#define W_OFF   16384
#define STAGE_B 32768
#define NSTAGE  3
#define SMEM_TOTAL (NSTAGE * STAGE_B)
#define NCHUNK  65

__device__ __forceinline__ void issue_stage(uint32_t st, int ch, int m0, int n0, int tid)
{
    const int r8 = tid >> 3, sg = tid & 7;
    const size_t kofs = (size_t)ch * 64 + sg * 8;
    const uint32_t sgb = (uint32_t)sg * 16u;
    #pragma unroll
    for (int j = 0; j < 4; j++) {
        int row = r8 + 32 * j;
        uint32_t d = (uint32_t)row * 128u + (sgb ^ ((uint32_t)(row & 7) << 4));
        cpa16(st + A_OFF + d, g_xp + (size_t)(m0 + row) * KE + kofs);
    }
    #pragma unroll
    for (int j = 0; j < 4; j++) {
        int row = r8 + 32 * j;
        uint32_t d = (uint32_t)row * 128u + (sgb ^ ((uint32_t)(row & 7) << 4));
        cpa16(st + W_OFF + d, g_wp + (size_t)(n0 + row) * KE + kofs);
    }
    asm volatile("cp.async.commit_group;" ::: "memory");
}

__global__ void __launch_bounds__(256, 2) fused_gemm_kernel(float* __restrict__ out)
{
    extern __shared__ char smem[];
    const int tid = threadIdx.x;
    const int wid = tid >> 5, lid = tid & 31;
    const int wr = wid >> 1, wc = wid & 1;
    const int n0 = blockIdx.x * 128;
    const int m0 = blockIdx.y * 128;
    const uint32_t sbase = smem_u32(smem);
    const int lr = lid & 15;
    const uint32_t lhb = (uint32_t)(lid >> 4) * 16u;

    uint32_t abase[2], arx[2], bbase[4], brx[4];
    #pragma unroll
    for (int t = 0; t < 2; t++) {
        uint32_t row = (uint32_t)(wr * 32 + t * 16 + lr);
        abase[t] = row * 128u; arx[t] = (row & 7u) << 4;
    }
    #pragma unroll
    for (int g = 0; g < 4; g++) {
        uint32_t row = (uint32_t)(wc * 64 + g * 16 + lr);
        bbase[g] = row * 128u; brx[g] = (row & 7u) << 4;
    }

    float acc[2][8][4];
    #pragma unroll
    for (int t = 0; t < 2; t++)
        #pragma unroll
        for (int j = 0; j < 8; j++)
            #pragma unroll
            for (int e = 0; e < 4; e++) acc[t][j][e] = 0.f;

    issue_stage(sbase + 0 * STAGE_B, 0, m0, n0, tid);
    issue_stage(sbase + 1 * STAGE_B, 1, m0, n0, tid);

    int sidx = 0;
    for (int ch = 0; ch < NCHUNK; ch++) {
        const uint32_t st = sbase + sidx * STAGE_B;
        const uint32_t sa = st + A_OFF, sw = st + W_OFF;

        asm volatile("cp.async.wait_group 1;" ::: "memory");
        __syncthreads();
        if (ch + 2 < NCHUNK) {
            int ps = sidx + 2; if (ps >= NSTAGE) ps -= NSTAGE;
            issue_stage(sbase + ps * STAGE_B, ch + 2, m0, n0, tid);
        } else {
            asm volatile("cp.async.commit_group;" ::: "memory");
        }

        #pragma unroll
        for (int ks = 0; ks < 4; ks++) {
            const uint32_t chb = (uint32_t)ks * 32u + lhb;
            uint32_t ah[2][4];
            ldm4(ah[0], sa + abase[0] + (chb ^ arx[0]));
            ldm4(ah[1], sa + abase[1] + (chb ^ arx[1]));

            uint32_t bfrag[2][4];
            ldm4(bfrag[0], sw + bbase[0] + (chb ^ brx[0]));
            #pragma unroll
            for (int g = 0; g < 4; g++) {
                const int cur = g & 1;
                if (g < 3)
                    ldm4(bfrag[cur ^ 1], sw + bbase[g + 1] + (chb ^ brx[g + 1]));
                #pragma unroll
                for (int t = 0; t < 2; t++) {
                    #pragma unroll
                    for (int j2 = 0; j2 < 2; j2++)
                        mma16816(acc[t][g * 2 + j2], ah[t],
                                 bfrag[cur][j2], bfrag[cur][j2 + 2]);
                }
            }
        }
        if (++sidx >= NSTAGE) sidx = 0;
    }

    #pragma unroll
    for (int t = 0; t < 2; t++) {
        int mr = m0 + wr * 32 + t * 16 + (lid >> 2);
        #pragma unroll
        for (int j = 0; j < 8; j++) {
            int col = n0 + wc * 64 + j * 8 + (lid & 3) * 2;
            *reinterpret_cast<float2*>(out + (size_t)mr * HOUT + col) =
                make_float2(acc[t][j][0], acc[t][j][1]);
            *reinterpret_cast<float2*>(out + (size_t)(mr + 8) * HOUT + col) =
                make_float2(acc[t][j][2], acc[t][j][3]);
        }
    }
}

// ================= launch =================
extern "C" void kernel_launch(void* const* d_in, const int* in_sizes, int n_in,
                              void* d_out, int out_size) {
    const float* x       = (const float*)d_in[0];
    const float* tkw     = (const float*)d_in[1];
    const float* W       = (const float*)d_in[2];
    const float* qa      = (const float*)d_in[3];
    const float* qb      = (const float*)d_in[4];
    const float* scaling = (const float*)d_in[5];
    float* out = (float*)d_out;

    cvt_qa_kernel<<<32, 256>>>(qa);
    prep_kernel<<<NLORA_BLK + HOUT / 8, 256>>>(x, tkw, W, qb, scaling);

    cudaFuncSetAttribute(fused_gemm_kernel,
                         cudaFuncAttributeMaxDynamicSharedMemorySize, SMEM_TOTAL);
    dim3 grid(HOUT / 128, B_DIM / 128);
    fused_gemm_kernel<<<grid, 256, SMEM_TOTAL>>>(out);
}